// round 11
// baseline (speedup 1.0000x reference)
#include <cuda_runtime.h>

// Problem constants (from reference): N=1048576 rows, H=128, B=1024 segments.
#define H_DIM 128
#define EPS 1e-12f
#define MAX_B 4096          // scratch sized generously vs B=1024
#define MAX_N (1 << 20)     // N = 1048576

// Precomputed w[s,h] = d[h] * summary[s,h]  (512KB for B=1024)
__device__ float g_wbuf[MAX_B * H_DIM];
// Precomputed row -> segment id (2MB for N=1M)
__device__ unsigned short g_seg[MAX_N];
// Grid-barrier arrive counter. Monotonic across launches/replays: each launch
// adds exactly gridDim.x, so the release target is the next multiple of
// gridDim.x — no reset required, fully deterministic.
__device__ unsigned g_arrive = 0;

// Single persistent kernel: phase 0 builds g_wbuf + g_seg, a software grid
// barrier (legal: launch_bounds(256,6) + grid == SMs*6 makes all blocks
// co-resident), then the streaming sim phase.
__global__ void __launch_bounds__(256, 6) fused_kernel(
    const float* __restrict__ emb,
    const float* __restrict__ summary,
    const int*   __restrict__ ptr,      // int32 (JAX x64 disabled)
    const float* __restrict__ dvec,
    const float* __restrict__ scale,
    float* __restrict__ out,
    int n_rows, int n_seg, int w_total)
{
    const int tid = threadIdx.x;

    // ---------------- Phase 0a: w = d (*) summary ----------------
    for (int i = blockIdx.x * 256 + tid; i < w_total; i += gridDim.x * 256)
        g_wbuf[i] = summary[i] * dvec[i & (H_DIM - 1)];

    // ---------------- Phase 0b: seg table (vectorized u16 fill) ----------------
    for (int s = blockIdx.x; s < n_seg; s += gridDim.x) {
        const int start = ptr[s];
        const int end   = min(ptr[s + 1], n_rows);
        const unsigned short sval = (unsigned short)s;
        const unsigned v2 = (unsigned)sval * 0x00010001u;

        const int ahead = min(end, (start + 7) & ~7);           // head to 8-align
        for (int i = start + tid; i < ahead; i += 256) g_seg[i] = sval;

        const int bend = max(ahead, end & ~7);                  // vector body end
        uint4* seg4 = reinterpret_cast<uint4*>(g_seg);
        const uint4 v4 = make_uint4(v2, v2, v2, v2);
        for (int i = ahead / 8 + tid; i < bend / 8; i += 256) seg4[i] = v4;

        for (int i = bend + tid; i < end; i += 256) g_seg[i] = sval;  // tail
    }

    // ---------------- Grid barrier ----------------
    __threadfence();
    __syncthreads();
    if (tid == 0) {
        const unsigned old    = atomicAdd(&g_arrive, 1u);
        const unsigned target = old - (old % gridDim.x) + gridDim.x;
        while (*(volatile unsigned*)&g_arrive < target)
            __nanosleep(64);
        __threadfence();
    }
    __syncthreads();

    // ---------------- Phase 1: streaming sim ----------------
    // 4 rows per warp per iteration; each 8-lane group owns one row.
    // Lane g holds float4 columns {g, g+8, g+16, g+24}: four FULL 128B lines
    // per warp-load. e-loads front-batched; w loads are L2 hits.
    const int wid  = (blockIdx.x * 256 + tid) >> 5;
    const int lane = tid & 31;
    const int g    = lane & 7;
    const int rsub = lane >> 3;
    const int stride_rows = gridDim.x * 8 * 4;
    const float sc = __ldg(scale);

    for (int base = wid * 4; base < n_rows; base += stride_rows) {
        int row = base + rsub;
        const bool valid = row < n_rows;
        row = min(row, n_rows - 1);

        const int seg = (int)g_seg[row];

        const float4* e4 = reinterpret_cast<const float4*>(emb)    + (size_t)row * (H_DIM / 4);
        const float4* w4 = reinterpret_cast<const float4*>(g_wbuf) + (size_t)seg * (H_DIM / 4);

        const float4 e0 = __ldcs(&e4[g]);
        const float4 e1 = __ldcs(&e4[8 + g]);
        const float4 e2 = __ldcs(&e4[16 + g]);
        const float4 e3 = __ldcs(&e4[24 + g]);

        float ds;
        ds = e0.x * e0.x;
        ds = fmaf(e0.y, e0.y, ds); ds = fmaf(e0.z, e0.z, ds); ds = fmaf(e0.w, e0.w, ds);
        ds = fmaf(e1.x, e1.x, ds); ds = fmaf(e1.y, e1.y, ds);
        ds = fmaf(e1.z, e1.z, ds); ds = fmaf(e1.w, e1.w, ds);
        ds = fmaf(e2.x, e2.x, ds); ds = fmaf(e2.y, e2.y, ds);
        ds = fmaf(e2.z, e2.z, ds); ds = fmaf(e2.w, e2.w, ds);
        ds = fmaf(e3.x, e3.x, ds); ds = fmaf(e3.y, e3.y, ds);
        ds = fmaf(e3.z, e3.z, ds); ds = fmaf(e3.w, e3.w, ds);

        float dw;
        {
            const float4 w = __ldg(&w4[g]);
            dw = e0.x * w.x;
            dw = fmaf(e0.y, w.y, dw); dw = fmaf(e0.z, w.z, dw); dw = fmaf(e0.w, w.w, dw);
        }
        {
            const float4 w = __ldg(&w4[8 + g]);
            dw = fmaf(e1.x, w.x, dw); dw = fmaf(e1.y, w.y, dw);
            dw = fmaf(e1.z, w.z, dw); dw = fmaf(e1.w, w.w, dw);
        }
        {
            const float4 w = __ldg(&w4[16 + g]);
            dw = fmaf(e2.x, w.x, dw); dw = fmaf(e2.y, w.y, dw);
            dw = fmaf(e2.z, w.z, dw); dw = fmaf(e2.w, w.w, dw);
        }
        {
            const float4 w = __ldg(&w4[24 + g]);
            dw = fmaf(e3.x, w.x, dw); dw = fmaf(e3.y, w.y, dw);
            dw = fmaf(e3.z, w.z, dw); dw = fmaf(e3.w, w.w, dw);
        }

        #pragma unroll
        for (int off = 4; off > 0; off >>= 1) {
            ds += __shfl_xor_sync(0xFFFFFFFFu, ds, off);
            dw += __shfl_xor_sync(0xFFFFFFFFu, dw, off);
        }

        if (g == 0 && valid) {
            __stcs(&out[row], sc * __fdividef(dw, fmaxf(sqrtf(ds), EPS)));
        }
    }
}

extern "C" void kernel_launch(void* const* d_in, const int* in_sizes, int n_in,
                              void* d_out, int out_size)
{
    const float* emb     = (const float*)d_in[0];   // [N, H]
    const float* summary = (const float*)d_in[1];   // [B, H]
    const int*   ptr     = (const int*)d_in[2];     // [B+1] int32
    const float* dvec    = (const float*)d_in[3];   // [H]
    const float* scale   = (const float*)d_in[4];   // [1]
    float*       out     = (float*)d_out;           // [N]

    const int n_rows  = in_sizes[0] / H_DIM;   // N
    const int n_seg   = in_sizes[2] - 1;       // B
    const int w_total = in_sizes[1];           // B*H

    // Grid must equal SMs * 6 so every block is co-resident (barrier safety).
    int dev = 0, sms = 148;
    cudaGetDevice(&dev);
    cudaDeviceGetAttribute(&sms, cudaDevAttrMultiProcessorCount, dev);
    const int blocks = sms * 6;

    fused_kernel<<<blocks, 256>>>(emb, summary, ptr, dvec, scale, out,
                                  n_rows, n_seg, w_total);
}

// round 12
// speedup vs baseline: 1.0362x; 1.0362x over previous
#include <cuda_runtime.h>

// Problem constants (from reference): N=1048576 rows, H=128, B=1024 segments.
#define H_DIM 128
#define EPS 1e-12f
#define MAX_B 4096          // scratch sized generously vs B=1024
#define MAX_N (1 << 20)     // N = 1048576

// Precomputed w[s,h] = d[h] * summary[s,h]  (512KB for B=1024)
__device__ float g_wbuf[MAX_B * H_DIM];
// Precomputed row -> segment id (2MB for N=1M)
__device__ unsigned short g_seg[MAX_N];

// Fused prep: blocks [0, n_seg) fill the seg table (one block per segment,
// vectorized u16 stores), blocks [n_seg, ...) compute w = d (*) summary.
__global__ void __launch_bounds__(256) prep_kernel(
    const float* __restrict__ summary,
    const float* __restrict__ dvec,
    const int*   __restrict__ ptr,
    int n_rows, int n_seg, int w_total)
{
    const int b   = blockIdx.x;
    const int tid = threadIdx.x;
    if (b < n_seg) {
        const int start = ptr[b];
        const int end   = min(ptr[b + 1], n_rows);
        const unsigned short sval = (unsigned short)b;
        const unsigned v2 = (unsigned)sval * 0x00010001u;

        const int ahead = min(end, (start + 7) & ~7);           // head to 8-align
        for (int i = start + tid; i < ahead; i += 256) g_seg[i] = sval;

        const int bend = max(ahead, end & ~7);                  // vector body end
        uint4* seg4 = reinterpret_cast<uint4*>(g_seg);
        const uint4 v4 = make_uint4(v2, v2, v2, v2);
        for (int i = ahead / 8 + tid; i < bend / 8; i += 256) seg4[i] = v4;

        for (int i = bend + tid; i < end; i += 256) g_seg[i] = sval;  // tail
    } else {
        const int i = (b - n_seg) * 256 + tid;
        if (i < w_total)
            g_wbuf[i] = summary[i] * dvec[i & (H_DIM - 1)];
    }
}

// Persistent streaming kernel (PDL consumer). Launch/prologue overlaps the
// prep kernel; cudaGridDependencySynchronize() gates only the first access
// to g_seg / g_wbuf.
// 4 rows per warp per iteration; each 8-lane group owns one row. Lane g
// holds float4 columns {g, g+8, g+16, g+24}: four FULL 128B lines per
// warp-load. e-loads front-batched; w loads are L2 hits.
__global__ void __launch_bounds__(256, 6) sim_kernel(
    const float* __restrict__ emb,
    const float* __restrict__ scale,
    float* __restrict__ out,
    int n_rows, int stride_rows)
{
    const int wid  = (blockIdx.x * blockDim.x + threadIdx.x) >> 5;
    const int lane = threadIdx.x & 31;
    const int g    = lane & 7;        // position within 8-lane row group
    const int rsub = lane >> 3;       // which of the warp's 4 rows
    const float sc = __ldg(scale);    // independent of prep outputs

    // Wait for prep's g_seg / g_wbuf writes to be visible.
    cudaGridDependencySynchronize();

    for (int base = wid * 4; base < n_rows; base += stride_rows) {
        int row = base + rsub;
        const bool valid = row < n_rows;
        row = min(row, n_rows - 1);

        const int seg = (int)g_seg[row];

        const float4* e4 = reinterpret_cast<const float4*>(emb)    + (size_t)row * (H_DIM / 4);
        const float4* w4 = reinterpret_cast<const float4*>(g_wbuf) + (size_t)seg * (H_DIM / 4);

        // ---- all 4 streaming loads front-batched ----
        const float4 e0 = __ldcs(&e4[g]);
        const float4 e1 = __ldcs(&e4[8 + g]);
        const float4 e2 = __ldcs(&e4[16 + g]);
        const float4 e3 = __ldcs(&e4[24 + g]);

        // Self-dot (norm) — consumes e as it lands.
        float ds;
        ds = e0.x * e0.x;
        ds = fmaf(e0.y, e0.y, ds); ds = fmaf(e0.z, e0.z, ds); ds = fmaf(e0.w, e0.w, ds);
        ds = fmaf(e1.x, e1.x, ds); ds = fmaf(e1.y, e1.y, ds);
        ds = fmaf(e1.z, e1.z, ds); ds = fmaf(e1.w, e1.w, ds);
        ds = fmaf(e2.x, e2.x, ds); ds = fmaf(e2.y, e2.y, ds);
        ds = fmaf(e2.z, e2.z, ds); ds = fmaf(e2.w, e2.w, ds);
        ds = fmaf(e3.x, e3.x, ds); ds = fmaf(e3.y, e3.y, ds);
        ds = fmaf(e3.z, e3.z, ds); ds = fmaf(e3.w, e3.w, ds);

        // Weighted dot — one float4 of w live at a time (L1/L2 hits).
        float dw;
        {
            const float4 w = __ldg(&w4[g]);
            dw = e0.x * w.x;
            dw = fmaf(e0.y, w.y, dw); dw = fmaf(e0.z, w.z, dw); dw = fmaf(e0.w, w.w, dw);
        }
        {
            const float4 w = __ldg(&w4[8 + g]);
            dw = fmaf(e1.x, w.x, dw); dw = fmaf(e1.y, w.y, dw);
            dw = fmaf(e1.z, w.z, dw); dw = fmaf(e1.w, w.w, dw);
        }
        {
            const float4 w = __ldg(&w4[16 + g]);
            dw = fmaf(e2.x, w.x, dw); dw = fmaf(e2.y, w.y, dw);
            dw = fmaf(e2.z, w.z, dw); dw = fmaf(e2.w, w.w, dw);
        }
        {
            const float4 w = __ldg(&w4[24 + g]);
            dw = fmaf(e3.x, w.x, dw); dw = fmaf(e3.y, w.y, dw);
            dw = fmaf(e3.z, w.z, dw); dw = fmaf(e3.w, w.w, dw);
        }

        // Reduce within each 8-lane group (3 butterfly steps, both sums).
        #pragma unroll
        for (int off = 4; off > 0; off >>= 1) {
            ds += __shfl_xor_sync(0xFFFFFFFFu, ds, off);
            dw += __shfl_xor_sync(0xFFFFFFFFu, dw, off);
        }

        if (g == 0 && valid) {
            __stcs(&out[row], sc * __fdividef(dw, fmaxf(sqrtf(ds), EPS)));
        }
    }
}

extern "C" void kernel_launch(void* const* d_in, const int* in_sizes, int n_in,
                              void* d_out, int out_size)
{
    const float* emb     = (const float*)d_in[0];   // [N, H]
    const float* summary = (const float*)d_in[1];   // [B, H]
    const int*   ptr     = (const int*)d_in[2];     // [B+1] int32
    const float* dvec    = (const float*)d_in[3];   // [H]
    const float* scale   = (const float*)d_in[4];   // [1]
    float*       out     = (float*)d_out;           // [N]

    const int n_rows  = in_sizes[0] / H_DIM;   // N
    const int n_seg   = in_sizes[2] - 1;       // B
    const int w_total = in_sizes[1];           // B*H

    const int w_blocks = (w_total + 255) / 256;
    prep_kernel<<<n_seg + w_blocks, 256>>>(summary, dvec, ptr, n_rows, n_seg, w_total);

    // Persistent sim, launched with PDL so its prologue overlaps prep.
    int dev = 0, sms = 148;
    cudaGetDevice(&dev);
    cudaDeviceGetAttribute(&sms, cudaDevAttrMultiProcessorCount, dev);
    const int blocks      = sms * 6;
    const int stride_rows = blocks * 8 * 4;   // 8 warps/block, 4 rows/warp/iter

    cudaLaunchConfig_t cfg = {};
    cfg.gridDim  = dim3((unsigned)blocks, 1, 1);
    cfg.blockDim = dim3(256, 1, 1);
    cfg.dynamicSmemBytes = 0;
    cfg.stream = 0;
    cudaLaunchAttribute attrs[1];
    attrs[0].id = cudaLaunchAttributeProgrammaticStreamSerialization;
    attrs[0].val.programmaticStreamSerializationAllowed = 1;
    cfg.attrs = attrs;
    cfg.numAttrs = 1;

    cudaLaunchKernelEx(&cfg, sim_kernel, emb, scale, out, n_rows, stride_rows);
}